// round 1
// baseline (speedup 1.0000x reference)
#include <cuda_runtime.h>
#include <math.h>

#define BATCH    16
#define NBOX     120000
#define NCH      22
#define NMS_MAX  400
#define NUM_PRED 10
#define BINS     4096
#define CAP      2048
#define MASKW    7          // ceil(400/64)

// ---------------- scratch (device globals; no allocation allowed) ------------
__device__ unsigned int       g_hist[BATCH][BINS];
__device__ int                g_cnt[BATCH];
__device__ int                g_cut[BATCH];
__device__ float              g_scores[BATCH][NBOX];
__device__ unsigned long long g_cand[BATCH][CAP];
__device__ unsigned long long g_top[BATCH][NMS_MAX];

// monotonic float->uint key (handles any sign, though scores are >=0 here)
__device__ __forceinline__ unsigned int fkey(float f) {
    unsigned int u = __float_as_uint(f);
    return (u & 0x80000000u) ? ~u : (u | 0x80000000u);
}
__device__ __forceinline__ float fkey_inv(unsigned int k) {
    unsigned int u = (k & 0x80000000u) ? (k & 0x7fffffffu) : ~k;
    return __uint_as_float(u);
}
__device__ __forceinline__ int score_bin(float s) {
    int b = (int)(s * 4096.0f);
    if (b < 0) b = 0;
    if (b > BINS - 1) b = BINS - 1;
    return b;
}

// ---------------- kernel 0: zero counters --------------------------------
__global__ void k_zero() {
    int t = blockIdx.x * blockDim.x + threadIdx.x;
    int total = BATCH * BINS;
    if (t < total) ((unsigned int*)g_hist)[t] = 0u;
    if (t < BATCH) g_cnt[t] = 0;
}

// ---------------- kernel 1: score extract + histogram --------------------
__global__ void k_hist(const float* __restrict__ y) {
    __shared__ unsigned int sh[BINS];
    int b = blockIdx.y;
    for (int i = threadIdx.x; i < BINS; i += blockDim.x) sh[i] = 0u;
    __syncthreads();
    const float* base = y + (size_t)b * NBOX * NCH;
    int stride = gridDim.x * blockDim.x;
    for (int i = blockIdx.x * blockDim.x + threadIdx.x; i < NBOX; i += stride) {
        float s = base[(size_t)i * NCH + 1];
        g_scores[b][i] = s;
        atomicAdd(&sh[score_bin(s)], 1u);
    }
    __syncthreads();
    for (int i = threadIdx.x; i < BINS; i += blockDim.x)
        if (sh[i]) atomicAdd(&g_hist[b][i], sh[i]);
}

// ---------------- kernel 2: pick cutoff bin per batch ---------------------
__global__ void k_cutoff() {
    int b = threadIdx.x;
    if (b < BATCH) {
        int cum = 0, cut = 0;
        for (int i = BINS - 1; i >= 0; --i) {
            cum += (int)g_hist[b][i];
            if (cum >= NMS_MAX) { cut = i; break; }
        }
        g_cut[b] = cut;
    }
}

// ---------------- kernel 3: gather candidates ----------------------------
__global__ void k_gather() {
    int b = blockIdx.y;
    int cut = g_cut[b];
    int stride = gridDim.x * blockDim.x;
    for (int i = blockIdx.x * blockDim.x + threadIdx.x; i < NBOX; i += stride) {
        float s = g_scores[b][i];
        if (score_bin(s) >= cut) {
            int p = atomicAdd(&g_cnt[b], 1);
            if (p < CAP) {
                unsigned long long key =
                    ((unsigned long long)fkey(s) << 32) |
                    (unsigned long long)(~(unsigned int)i);
                g_cand[b][p] = key;
            }
        }
    }
}

// ---------------- kernel 4: bitonic sort, keep top-400 --------------------
__global__ void k_sort() {
    __shared__ unsigned long long s[CAP];
    int b = blockIdx.x;
    int cnt = g_cnt[b]; if (cnt > CAP) cnt = CAP;
    for (int i = threadIdx.x; i < CAP; i += blockDim.x)
        s[i] = (i < cnt) ? g_cand[b][i] : 0ULL;
    __syncthreads();
    for (int k = 2; k <= CAP; k <<= 1) {
        for (int j = k >> 1; j > 0; j >>= 1) {
            for (int i = threadIdx.x; i < CAP; i += blockDim.x) {
                int ixj = i ^ j;
                if (ixj > i) {
                    bool up = ((i & k) == 0);
                    unsigned long long a = s[i], c = s[ixj];
                    if (up ? (a > c) : (a < c)) { s[i] = c; s[ixj] = a; }
                }
            }
            __syncthreads();
        }
    }
    // ascending sort -> top-400 from the back, descending order
    for (int t = threadIdx.x; t < NMS_MAX; t += blockDim.x)
        g_top[b][t] = s[CAP - 1 - t];
}

// ---------------- kernel 5: decode + NMS + output -------------------------
__global__ void k_nms(const float* __restrict__ y, float* __restrict__ out) {
    __shared__ float sc[NMS_MAX];
    __shared__ float bx[NMS_MAX][4];
    __shared__ int   sidx[NMS_MAX];
    __shared__ unsigned long long ov[NMS_MAX][MASKW];
    __shared__ unsigned long long keepm[MASKW];
    __shared__ int sel[NUM_PRED];
    __shared__ int selk[NUM_PRED];

    int b   = blockIdx.x;
    int tid = threadIdx.x;

    // --- load top-400, decode corner boxes ---
    for (int t = tid; t < NMS_MAX; t += blockDim.x) {
        unsigned long long key = g_top[b][t];
        float s = fkey_inv((unsigned int)(key >> 32));
        unsigned int idx = ~(unsigned int)(key & 0xffffffffu);
        if (idx >= NBOX) idx = 0;  // safety (padded slot; cannot occur here)
        sc[t]   = s;
        sidx[t] = (int)idx;
        const float* r = y + ((size_t)b * NBOX + idx) * NCH;
        float l0 = r[2], l1 = r[3], l2 = r[4], l3 = r[5];
        float dcx = r[14], dcy = r[15], dw = r[16], dh = r[17];
        float v0 = r[18], v1 = r[19], v2 = r[20], v3 = r[21];
        float cx = l0 * v0 * dw + dcx;
        float cy = l1 * v1 * dh + dcy;
        float w  = expf(l2 * v2) * dw;
        float h  = expf(l3 * v3) * dh;
        bx[t][0] = (cx - w * 0.5f) * 384.0f;
        bx[t][1] = (cy - h * 0.5f) * 384.0f;
        bx[t][2] = (cx + w * 0.5f) * 384.0f;
        bx[t][3] = (cy + h * 0.5f) * 384.0f;
    }
    __syncthreads();

    // --- overlap bitmasks: one thread per (row, 64-wide word), no atomics ---
    for (int p = tid; p < NMS_MAX * MASKW; p += blockDim.x) {
        int i = p / MASKW, w = p % MASKW;
        float ax0 = bx[i][0], ay0 = bx[i][1], ax1 = bx[i][2], ay1 = bx[i][3];
        float areai = (ax1 - ax0) * (ay1 - ay0);
        unsigned long long m = 0ULL;
        int j0 = w * 64;
        int j1 = j0 + 64; if (j1 > NMS_MAX) j1 = NMS_MAX;
        for (int j = j0; j < j1; ++j) {
            float cx0 = bx[j][0], cy0 = bx[j][1], cx1 = bx[j][2], cy1 = bx[j][3];
            float lt0 = fmaxf(ax0, cx0), lt1 = fmaxf(ay0, cy0);
            float rb0 = fminf(ax1, cx1), rb1 = fminf(ay1, cy1);
            float w0 = fmaxf(rb0 - lt0, 0.0f);
            float w1 = fmaxf(rb1 - lt1, 0.0f);
            float inter = w0 * w1;
            float areaj = (cx1 - cx0) * (cy1 - cy0);
            float uni = areai + areaj - inter;
            float iou = inter / fmaxf(uni, 1e-8f);
            if (iou > 0.45f) m |= 1ULL << (j - j0);
        }
        ov[i][w] = m;
    }
    __syncthreads();

    // --- greedy NMS: warp 0, lanes 0..6 own the 7 keep words ---
    if (tid < 32) {
        int lane = tid;
        unsigned long long kp = 0ULL;
        for (int i = 0; i < NMS_MAX; ++i) {
            unsigned long long o = (lane < MASKW) ? ov[i][lane] : 0ULL;
            bool hit = (o & kp) != 0ULL;   // kp only has bits j < i
            bool sup = __any_sync(0xffffffffu, hit);
            bool val = sc[i] > 0.01f;
            if (val && !sup && lane == (i >> 6)) kp |= 1ULL << (i & 63);
        }
        if (lane < MASKW) keepm[lane] = kp;
    }
    __syncthreads();

    // --- selection: kept (score-desc order), then fill with non-kept asc ---
    if (tid == 0) {
        int c = 0;
        for (int i = 0; i < NMS_MAX && c < NUM_PRED; ++i)
            if ((keepm[i >> 6] >> (i & 63)) & 1ULL) { sel[c] = i; selk[c] = 1; ++c; }
        for (int i = 0; i < NMS_MAX && c < NUM_PRED; ++i)
            if (!((keepm[i >> 6] >> (i & 63)) & 1ULL)) { sel[c] = i; selk[c] = 0; ++c; }
    }
    __syncthreads();

    // --- output rows: [score, box4, quad8] ---
    if (tid < NUM_PRED) {
        int i = sel[tid];
        float score = selk[tid] ? sc[i] : -1.0f;
        float* o = out + ((size_t)b * NUM_PRED + tid) * 13;
        o[0] = score;
        o[1] = bx[i][0]; o[2] = bx[i][1]; o[3] = bx[i][2]; o[4] = bx[i][3];
        const float* r = y + ((size_t)b * NBOX + sidx[i]) * NCH;
        float dcx = r[14], dcy = r[15], dw = r[16], dh = r[17];
        float v0 = r[18], v1 = r[19];
        float dqx[4] = {dcx - dw * 0.5f, dcx + dw * 0.5f, dcx + dw * 0.5f, dcx - dw * 0.5f};
        float dqy[4] = {dcy - dh * 0.5f, dcy - dh * 0.5f, dcy + dh * 0.5f, dcy + dh * 0.5f};
#pragma unroll
        for (int k = 0; k < 4; ++k) {
            float qx = dqx[k] + r[6 + 2 * k] * v0 * dw;   // loc[4+2k] = y[2+4+2k]
            float qy = dqy[k] + r[7 + 2 * k] * v1 * dh;   // loc[5+2k]
            o[5 + 2 * k]     = qx * 384.0f;
            o[5 + 2 * k + 1] = qy * 384.0f;
        }
    }
}

// ---------------- launch ---------------------------------------------------
extern "C" void kernel_launch(void* const* d_in, const int* in_sizes, int n_in,
                              void* d_out, int out_size) {
    const float* y = (const float*)d_in[0];
    float* out = (float*)d_out;

    {
        int total = BATCH * BINS;
        int thr = 256;
        int blk = (total + thr - 1) / thr;
        k_zero<<<blk, thr>>>();
    }
    {
        dim3 grid(64, BATCH);
        k_hist<<<grid, 256>>>(y);
    }
    k_cutoff<<<1, 32>>>();
    {
        dim3 grid(64, BATCH);
        k_gather<<<grid, 256>>>();
    }
    k_sort<<<BATCH, 1024>>>();
    k_nms<<<BATCH, 512>>>(y, out);
}

// round 2
// speedup vs baseline: 1.2214x; 1.2214x over previous
#include <cuda_runtime.h>
#include <math.h>

#define BATCH    16
#define NBOX     120000
#define NCH      22
#define NMS_MAX  400
#define NUM_PRED 10
#define BINS     1024
#define HBLK     64          // K1 blocks per batch
#define CAP      2048
#define MASKW    7           // ceil(400/64)

// ---------------- scratch (device globals; zero-init, no runtime alloc) -----
__device__ float        g_scores[BATCH][NBOX];
__device__ unsigned int g_phist[BATCH][HBLK][BINS];   // fully overwritten each call

// monotonic float->uint key
__device__ __forceinline__ unsigned int fkey(float f) {
    unsigned int u = __float_as_uint(f);
    return (u & 0x80000000u) ? ~u : (u | 0x80000000u);
}
__device__ __forceinline__ float fkey_inv(unsigned int k) {
    unsigned int u = (k & 0x80000000u) ? (k & 0x7fffffffu) : ~k;
    return __uint_as_float(u);
}
__device__ __forceinline__ int score_bin(float s) {
    int b = (int)(s * (float)BINS);
    if (b < 0) b = 0;
    if (b > BINS - 1) b = BINS - 1;
    return b;
}

// ============ K1: score extraction + per-block histogram (no atomics to gmem)
__global__ void k_extract(const float* __restrict__ y) {
    __shared__ unsigned int sh[BINS];
    int b = blockIdx.y;
    for (int i = threadIdx.x; i < BINS; i += blockDim.x) sh[i] = 0u;
    __syncthreads();
    const float* base = y + (size_t)b * NBOX * NCH + 1;
    int stride = gridDim.x * blockDim.x;
    for (int i = blockIdx.x * blockDim.x + threadIdx.x; i < NBOX; i += stride) {
        float s = __ldcs(&base[(size_t)i * NCH]);
        g_scores[b][i] = s;
        atomicAdd(&sh[score_bin(s)], 1u);
    }
    __syncthreads();
    for (int i = threadIdx.x; i < BINS; i += blockDim.x)
        g_phist[b][blockIdx.x][i] = sh[i];
}

// ============ K2: cutoff + gather + sort + decode + NMS + output ============
// shared layout (manual aliasing inside one static buffer):
//   phase A:  hist u32[1024]  @ 0      (4 KB)
//             cand u64[2048]  @ 4096   (16 KB)        [gather + sort]
//   phase B:  ov   u64[400][7]@ 0      (22.4 KB)      [after extraction]
//   always:   sc   f32[400]   @ 22464
//             sidx i32[400]   @ 24064
//             bx   f32[400][4]@ 25664  (6.4 KB)
#define OFF_HIST 0
#define OFF_CAND 4096
#define OFF_OV   0
#define OFF_SC   22464
#define OFF_SIDX 24064
#define OFF_BX   25664
#define SMEM_SZ  (25664 + 6400)

__global__ __launch_bounds__(1024, 1)
void k_select_nms(const float* __restrict__ y, float* __restrict__ out) {
    __shared__ __align__(16) unsigned char buf[SMEM_SZ];
    __shared__ unsigned long long keepm[MASKW];
    __shared__ int sel[NUM_PRED], selk[NUM_PRED];
    __shared__ int s_cut, s_cnt, pp[MASKW + 1];

    unsigned int* hist       = (unsigned int*)(buf + OFF_HIST);
    unsigned long long* cand = (unsigned long long*)(buf + OFF_CAND);
    unsigned long long* ov   = (unsigned long long*)(buf + OFF_OV);
    float* sc                = (float*)(buf + OFF_SC);
    int*   sidx              = (int*)(buf + OFF_SIDX);
    float* bx                = (float*)(buf + OFF_BX);

    int b   = blockIdx.x;
    int tid = threadIdx.x;
    int lane = tid & 31;

    // --- sum partial histograms (thread t owns bin t) ---
    if (tid < BINS) {
        unsigned int s = 0;
#pragma unroll 8
        for (int k = 0; k < HBLK; ++k) s += g_phist[b][k][tid];
        hist[tid] = s;
    }
    if (tid == 0) s_cnt = 0;
    __syncthreads();

    // --- cutoff: warp 0 scans from top in 32-bin chunks ---
    if (tid < 32) {
        int cum = 0;
        int cut = 0;
        for (int base = BINS - 32; base >= 0; base -= 32) {
            int v = (int)hist[base + 31 - lane];   // lane 0 = highest bin
            int p = v;
#pragma unroll
            for (int o = 1; o < 32; o <<= 1) {
                int t = __shfl_up_sync(0xffffffffu, p, o);
                if (lane >= o) p += t;
            }
            unsigned ball = __ballot_sync(0xffffffffu, cum + p >= NMS_MAX);
            if (ball) {
                int l0 = __ffs(ball) - 1;
                cut = base + 31 - l0;
                break;
            }
            cum += __shfl_sync(0xffffffffu, p, 31);
        }
        if (lane == 0) s_cut = cut;
    }
    __syncthreads();
    int cut = s_cut;

    // --- gather candidates (float4 over compact L2-resident scores) ---
    {
        const float4* sp = (const float4*)g_scores[b];
        for (int i4 = tid; i4 < NBOX / 4; i4 += 1024) {
            float4 v = sp[i4];
            float vv[4] = {v.x, v.y, v.z, v.w};
#pragma unroll
            for (int k = 0; k < 4; ++k) {
                if (score_bin(vv[k]) >= cut) {
                    int p = atomicAdd(&s_cnt, 1);
                    if (p < CAP) {
                        unsigned int idx = (unsigned int)(i4 * 4 + k);
                        cand[p] = ((unsigned long long)fkey(vv[k]) << 32) |
                                  (unsigned long long)(~idx);
                    }
                }
            }
        }
    }
    __syncthreads();
    int cnt = s_cnt; if (cnt > CAP) cnt = CAP;
    int n = 1; while (n < cnt) n <<= 1;            // >= 512 always (cnt >= 400)
    for (int i = cnt + tid; i < n; i += 1024) cand[i] = 0ULL;
    __syncthreads();

    // --- bitonic sort, DESCENDING ---
    for (int k = 2; k <= n; k <<= 1) {
        for (int j = k >> 1; j > 0; j >>= 1) {
            for (int i = tid; i < n; i += 1024) {
                int ixj = i ^ j;
                if (ixj > i) {
                    bool up = ((i & k) == 0);
                    unsigned long long a = cand[i], c = cand[ixj];
                    if (up ? (a < c) : (a > c)) { cand[i] = c; cand[ixj] = a; }
                }
            }
            __syncthreads();
        }
    }

    // --- extract top-400, decode corner boxes ---
    if (tid < NMS_MAX) {
        unsigned long long key = cand[tid];
        float s = fkey_inv((unsigned int)(key >> 32));
        unsigned int idx = ~(unsigned int)(key & 0xffffffffu);
        if (idx >= NBOX) idx = 0;
        sc[tid] = s;
        sidx[tid] = (int)idx;
        const float* r = y + ((size_t)b * NBOX + idx) * NCH;
        float l0 = r[2], l1 = r[3], l2 = r[4], l3 = r[5];
        float dcx = r[14], dcy = r[15], dw = r[16], dh = r[17];
        float v0 = r[18], v1 = r[19], v2 = r[20], v3 = r[21];
        float cx = l0 * v0 * dw + dcx;
        float cy = l1 * v1 * dh + dcy;
        float w  = expf(l2 * v2) * dw;
        float h  = expf(l3 * v3) * dh;
        bx[tid * 4 + 0] = (cx - w * 0.5f) * 384.0f;
        bx[tid * 4 + 1] = (cy - h * 0.5f) * 384.0f;
        bx[tid * 4 + 2] = (cx + w * 0.5f) * 384.0f;
        bx[tid * 4 + 3] = (cy + h * 0.5f) * 384.0f;
    }
    __syncthreads();   // cand dead from here; ov may overlay it

    // --- overlap bitmasks (thread per (row, 64-word)) ---
    for (int p = tid; p < NMS_MAX * MASKW; p += 1024) {
        int i = p / MASKW, w = p % MASKW;
        float ax0 = bx[i*4+0], ay0 = bx[i*4+1], ax1 = bx[i*4+2], ay1 = bx[i*4+3];
        float areai = (ax1 - ax0) * (ay1 - ay0);
        unsigned long long m = 0ULL;
        int j0 = w * 64;
        int j1 = j0 + 64; if (j1 > NMS_MAX) j1 = NMS_MAX;
        for (int j = j0; j < j1; ++j) {
            float cx0 = bx[j*4+0], cy0 = bx[j*4+1], cx1 = bx[j*4+2], cy1 = bx[j*4+3];
            float lt0 = fmaxf(ax0, cx0), lt1 = fmaxf(ay0, cy0);
            float rb0 = fminf(ax1, cx1), rb1 = fminf(ay1, cy1);
            float w0 = fmaxf(rb0 - lt0, 0.0f);
            float w1 = fmaxf(rb1 - lt1, 0.0f);
            float inter = w0 * w1;
            float areaj = (cx1 - cx0) * (cy1 - cy0);
            float uni = areai + areaj - inter;
            if (inter / fmaxf(uni, 1e-8f) > 0.45f) m |= 1ULL << (j - j0);
        }
        ov[i * MASKW + w] = m;
    }
    __syncthreads();

    // --- greedy NMS: warp 0, lanes 0..6 own keep words ---
    if (tid < 32) {
        unsigned long long kp = 0ULL;
        for (int i = 0; i < NMS_MAX; ++i) {
            unsigned long long o = (lane < MASKW) ? ov[i * MASKW + lane] : 0ULL;
            bool sup = __any_sync(0xffffffffu, (o & kp) != 0ULL);
            if (sc[i] > 0.01f && !sup && lane == (i >> 6)) kp |= 1ULL << (i & 63);
        }
        if (lane < MASKW) keepm[lane] = kp;
    }
    __syncthreads();

    // --- parallel selection via popcounts ---
    if (tid == 0) {
        pp[0] = 0;
        for (int w = 0; w < MASKW; ++w)
            pp[w + 1] = pp[w] + __popcll(keepm[w]);
    }
    __syncthreads();
    if (tid < NMS_MAX) {
        int w = tid >> 6, bit = tid & 63;
        unsigned long long below = keepm[w] & ((bit == 0) ? 0ULL : ((~0ULL) >> (64 - bit)));
        int keptBefore = pp[w] + __popcll(below);
        bool kept = (keepm[w] >> bit) & 1ULL;
        int K = pp[MASKW];
        if (kept) {
            if (keptBefore < NUM_PRED) { sel[keptBefore] = tid; selk[keptBefore] = 1; }
        } else {
            int r = K + (tid - keptBefore);
            if (r < NUM_PRED) { sel[r] = tid; selk[r] = 0; }
        }
    }
    __syncthreads();

    // --- output rows: [score, box4, quad8] ---
    if (tid < NUM_PRED) {
        int i = sel[tid];
        float* o = out + ((size_t)b * NUM_PRED + tid) * 13;
        o[0] = selk[tid] ? sc[i] : -1.0f;
        o[1] = bx[i*4+0]; o[2] = bx[i*4+1]; o[3] = bx[i*4+2]; o[4] = bx[i*4+3];
        const float* r = y + ((size_t)b * NBOX + sidx[i]) * NCH;
        float dcx = r[14], dcy = r[15], dw = r[16], dh = r[17];
        float v0 = r[18], v1 = r[19];
        float dqx[4] = {dcx - dw*0.5f, dcx + dw*0.5f, dcx + dw*0.5f, dcx - dw*0.5f};
        float dqy[4] = {dcy - dh*0.5f, dcy - dh*0.5f, dcy + dh*0.5f, dcy + dh*0.5f};
#pragma unroll
        for (int k = 0; k < 4; ++k) {
            float qx = dqx[k] + r[6 + 2*k] * v0 * dw;
            float qy = dqy[k] + r[7 + 2*k] * v1 * dh;
            o[5 + 2*k]     = qx * 384.0f;
            o[5 + 2*k + 1] = qy * 384.0f;
        }
    }
}

// ---------------- launch ---------------------------------------------------
extern "C" void kernel_launch(void* const* d_in, const int* in_sizes, int n_in,
                              void* d_out, int out_size) {
    const float* y = (const float*)d_in[0];
    float* out = (float*)d_out;
    dim3 g1(HBLK, BATCH);
    k_extract<<<g1, 256>>>(y);
    k_select_nms<<<BATCH, 1024>>>(y, out);
}